// round 16
// baseline (speedup 1.0000x reference)
#include <cuda_runtime.h>

// x:      (4, 64, 128, 128) fp32  -> 256 independent 128x128 images
// weight: (4, 576, 128, 128) fp32 -> 9 taps per channel, tap k strided by H*W
// steps = 8
//
// TALL-TILE kernel (R15 with the output-gate fix):
//  - TH=24 output rows, region 40 rows, 20 warps (640 thr), V=2
//  - x read by LDG in the prologue (no x staging); weights TMA-staged
//    (9 issuer warps) + x L2-prefetch hint (issuer 9)
//  - guard rows eliminated: boundary tap weights zeroed (warp0 top tap,
//    warp19 bottom tap) + clamped row reads; smem zero-initialized once
//  - shrinking-band elision: warp g computes step s iff s < min(2g+1,39-2g)
//  - dynamic tile tickets (global atomic + reset kernel)
//  - OUTPUT GATE: warps 4..15 ONLY (region rows 8..31); R15's `warp>=4`
//    let halo warps 16..19 clobber neighbor tiles' rows -> 0.33 rel_err.

#define H      128
#define W      128
#define IMG    (H * W)
#define STEPS  8
#define TH     24
#define TPI    6            // tiles per image
#define NT     (256 * TPI)  // 1536
#define RROWS  40
#define THREADS 640

#define OFF_MBAR 0
#define OFF_TKT  16
#define OFF_BUF  1024
#define OFF_WS   (OFF_BUF + 2 * RROWS * W * 4)   // 1024 + 40960 = 41984
#define SMEM_TOTAL (OFF_WS + 9 * RROWS * W * 4)  // + 184320     = 226304

typedef unsigned long long u64;
typedef unsigned int u32;

__device__ u32 g_ticket;
__global__ void reset_ticket_kernel() { g_ticket = 0u; }

__device__ __forceinline__ u32 s2u(const void* p) {
    u32 a;
    asm("{ .reg .u64 t; cvta.to.shared.u64 t, %1; cvt.u32.u64 %0, t; }"
        : "=r"(a) : "l"(p));
    return a;
}
__device__ __forceinline__ u64 pk(float lo, float hi) {
    u64 r; asm("mov.b64 %0, {%1,%2};" : "=l"(r) : "f"(lo), "f"(hi)); return r;
}
__device__ __forceinline__ void upk(u64 v, float& lo, float& hi) {
    asm("mov.b64 {%0,%1}, %2;" : "=f"(lo), "=f"(hi) : "l"(v));
}
__device__ __forceinline__ void fma2(u64& d, u64 a, u64 b) {
    asm("fma.rn.f32x2 %0, %1, %2, %0;" : "+l"(d) : "l"(a), "l"(b));
}
__device__ __forceinline__ u64 mul2(u64 a, u64 b) {
    u64 d; asm("mul.rn.f32x2 %0, %1, %2;" : "=l"(d) : "l"(a), "l"(b)); return d;
}
__device__ __forceinline__ float shup(float v) { return __shfl_up_sync(0xffffffffu, v, 1); }
__device__ __forceinline__ float shdn(float v) { return __shfl_down_sync(0xffffffffu, v, 1); }

__device__ __forceinline__ void mbar_wait(u32 mbar, u32 parity) {
    asm volatile(
        "{\n\t.reg .pred P;\n\t"
        "W_%=:\n\t"
        "mbarrier.try_wait.parity.shared::cta.b64 P, [%0], %1, 0x989680;\n\t"
        "@P bra.uni D_%=;\n\t"
        "bra.uni W_%=;\n\t"
        "D_%=:\n\t}"
        :: "r"(mbar), "r"(parity) : "memory");
}
__device__ __forceinline__ void bulk_g2s(u32 dst, const void* src, u32 bytes, u32 mbar) {
    asm volatile(
        "cp.async.bulk.shared::cluster.global.mbarrier::complete_tx::bytes "
        "[%0], [%1], %2, [%3];"
        :: "r"(dst), "l"(src), "r"(bytes), "r"(mbar) : "memory");
}
__device__ __forceinline__ void l2pf(const void* p, u32 bytes) {
    asm volatile("cp.async.bulk.prefetch.L2.global [%0], %1;"
                 :: "l"(p), "r"(bytes) : "memory");
}

// Distributed prefetch: issuer k = 0..8 -> weight tap k via TMA (arrives on
// mbar, count 9); k = 9 -> x region L2 prefetch hint (no mbar).
__device__ __forceinline__ void issue_prefetch_k(int t, int k,
                                                 const float* x, const float* wgt,
                                                 u32 ws, u32 mbar) {
    const int img = t / TPI;
    const int t0  = (t % TPI) * TH;
    const int rlo = (t0 - 8 < 0) ? 0 : (t0 - 8);
    const int rhi = (t0 + 32 > H) ? H : (t0 + 32);
    const int nrows = rhi - rlo;
    const int droff = rlo - (t0 - 8);
    const u32 bytes = (u32)nrows * (W * 4);
    if (k < 9) {
        asm volatile("mbarrier.arrive.expect_tx.shared.b64 _, [%0], %1;"
                     :: "r"(mbar), "r"(bytes) : "memory");
        const float* src = wgt + ((size_t)(img * 9 + k) << 14) + rlo * W;
        bulk_g2s(ws + (u32)(k * RROWS + droff) * (W * 4), src, bytes, mbar);
    } else {
        l2pf(x + ((size_t)img << 14) + rlo * W, bytes);
    }
}

__global__ __launch_bounds__(THREADS, 1)
void diffusion_persist_kernel(const float* __restrict__ x,
                              const float* __restrict__ wgt,
                              float* __restrict__ out)
{
    extern __shared__ char smem[];
    float (*buf)[RROWS][W] = (float (*)[RROWS][W])(smem + OFF_BUF);
    const float* wsp = (const float*)(smem + OFF_WS);
    volatile u32* tkt = (volatile u32*)(smem + OFF_TKT);
    const u32 mbar = s2u(smem + OFF_MBAR);
    const u32 ws_a = s2u(smem + OFF_WS);

    const int tid  = threadIdx.x;
    const int lane = tid & 31;
    const int warp = tid >> 5;          // 0..19; owns region rows 2g, 2g+1
    const int col0 = lane << 2;
    const int g2   = warp * 2;
    const int colL = (lane == 0)  ? col0     : col0 - 1;   // zeroed weights
    const int colR = (lane == 31) ? col0 + 3 : col0 + 4;   // zeroed weights
    const int rA   = (warp == 0)  ? 0          : g2 - 1;   // clamped rows:
    const int rB   = (warp == 19) ? RROWS - 1  : g2 + 2;   // zeroed tap wgts
    const bool issuer = (lane == 0 && warp < 10);
    // shrinking-band bound: compute step s iff s < nmax
    const int nmax = (g2 + 1 < 39 - g2) ? (g2 + 1) : (39 - g2);

    // one-time: zero the whole buf (garbage must be finite for 0-weight taps)
    for (int i = tid; i < 2 * RROWS * W / 4; i += THREADS)
        ((float4*)(smem + OFF_BUF))[i] = make_float4(0.f, 0.f, 0.f, 0.f);
    if (tid == 0) {
        asm volatile("mbarrier.init.shared.b64 [%0], 9;" :: "r"(mbar) : "memory");
        *tkt = atomicAdd(&g_ticket, 1u);
    }
    __syncthreads();

    int t = (int)*tkt;
    if (issuer && t < NT) issue_prefetch_k(t, warp, x, wgt, ws_a, mbar);
    u32 ph = 0;

    while (t < NT) {
        mbar_wait(mbar, ph); ph ^= 1u;
        if (tid == 0) *tkt = atomicAdd(&g_ticket, 1u);   // draw next tile

        const int img = t / TPI;
        const int t0  = (t % TPI) * TH;

        // ---- prologue: x via LDG (issued first), weights from staging
        u64 Wp[2][3][6];
        float4 y0, y1;
        {
            const int grow0 = t0 - 8 + g2;
            const int grow1 = grow0 + 1;
            const bool rv0 = ((unsigned)grow0 < (unsigned)H);
            const bool rv1 = ((unsigned)grow1 < (unsigned)H);
            y0 = make_float4(0.f, 0.f, 0.f, 0.f);
            y1 = make_float4(0.f, 0.f, 0.f, 0.f);
            if (rv0) y0 = __ldg((const float4*)(x + ((size_t)img << 14) + grow0 * W + col0));
            if (rv1) y1 = __ldg((const float4*)(x + ((size_t)img << 14) + grow1 * W + col0));
        }
#pragma unroll
        for (int ro = 0; ro < 2; ro++) {
            const int rr   = g2 + ro;
            const int grow = t0 - 8 + rr;
            const bool rv  = ((unsigned)grow < (unsigned)H);
            float aa[9][4];
            if (rv) {
                float s0 = 0.f, s1 = 0.f, s2 = 0.f, s3 = 0.f;
#pragma unroll
                for (int k = 0; k < 9; k++) {
                    float4 tv = *(const float4*)&wsp[(k * RROWS + rr) * W + col0];
                    aa[k][0] = fabsf(tv.x); aa[k][1] = fabsf(tv.y);
                    aa[k][2] = fabsf(tv.z); aa[k][3] = fabsf(tv.w);
                    s0 += aa[k][0]; s1 += aa[k][1]; s2 += aa[k][2]; s3 += aa[k][3];
                }
                const float i0 = __fdividef(1.f, s0), i1 = __fdividef(1.f, s1);
                const float i2 = __fdividef(1.f, s2), i3 = __fdividef(1.f, s3);
#pragma unroll
                for (int k = 0; k < 9; k++) {
                    aa[k][0] *= i0; aa[k][1] *= i1; aa[k][2] *= i2; aa[k][3] *= i3;
                }
                if (lane == 0)  { aa[0][0] = 0.f; aa[3][0] = 0.f; aa[6][0] = 0.f; }
                if (lane == 31) { aa[2][3] = 0.f; aa[5][3] = 0.f; aa[8][3] = 0.f; }
            } else {
#pragma unroll
                for (int k = 0; k < 9; k++) {
                    aa[k][0] = 0.f; aa[k][1] = 0.f; aa[k][2] = 0.f; aa[k][3] = 0.f;
                }
            }
#pragma unroll
            for (int ki = 0; ki < 3; ki++) {
                Wp[ro][ki][0] = pk(aa[ki * 3 + 0][0], aa[ki * 3 + 0][1]);
                Wp[ro][ki][1] = pk(aa[ki * 3 + 1][0], aa[ki * 3 + 1][1]);
                Wp[ro][ki][2] = pk(aa[ki * 3 + 2][0], aa[ki * 3 + 2][1]);
                Wp[ro][ki][3] = pk(aa[ki * 3 + 0][2], aa[ki * 3 + 0][3]);
                Wp[ro][ki][4] = pk(aa[ki * 3 + 1][2], aa[ki * 3 + 1][3]);
                Wp[ro][ki][5] = pk(aa[ki * 3 + 2][2], aa[ki * 3 + 2][3]);
            }
        }
        // boundary tap-weight zeroing (replaces guard rows; clamped reads OK)
        if (warp == 0) {
#pragma unroll
            for (int j = 0; j < 6; j++) Wp[0][0][j] = 0ull;   // row g2 top tap
        }
        if (warp == 19) {
#pragma unroll
            for (int j = 0; j < 6; j++) Wp[1][2][j] = 0ull;   // row g2+1 bot tap
        }
        *(float4*)&buf[0][g2][col0]     = y0;
        *(float4*)&buf[0][g2 + 1][col0] = y1;
        __syncthreads();   // staging consumed + buf[0] published + tkt visible

        const int tn = (int)*tkt;
        if (issuer && tn < NT) issue_prefetch_k(tn, warp, x, wgt, ws_a, mbar);

        // ---- 8 fused steps with shrinking-band elision
#pragma unroll
        for (int s = 0; s < STEPS; s++) {
            if (s < nmax) {
                const int cb = s & 1;
                const float* rowA = &buf[cb][rA][0];
                const float* rowB = &buf[cb][rB][0];
                float4 va = *(const float4*)&rowA[col0];
                const float vaL = rowA[colL], vaR = rowA[colR];
                float4 vb = *(const float4*)&rowB[col0];
                const float vbL = rowB[colL], vbR = rowB[colR];

                const float xl0 = shup(y0.w), xr0 = shdn(y0.x);
                const float xl1 = shup(y1.w), xr1 = shdn(y1.x);

                const u64 p00 = pk(xl0, y0.x), p01 = pk(y0.x, y0.y), p02 = pk(y0.y, y0.z);
                const u64 p03 = pk(y0.z, y0.w), p04 = pk(y0.w, xr0);
                const u64 p10 = pk(xl1, y1.x), p11 = pk(y1.x, y1.y), p12 = pk(y1.y, y1.z);
                const u64 p13 = pk(y1.z, y1.w), p14 = pk(y1.w, xr1);
                const u64 pA0 = pk(vaL, va.x), pA1 = pk(va.x, va.y), pA2 = pk(va.y, va.z);
                const u64 pA3 = pk(va.z, va.w), pA4 = pk(va.w, vaR);
                const u64 pB0 = pk(vbL, vb.x), pB1 = pk(vb.x, vb.y), pB2 = pk(vb.y, vb.z);
                const u64 pB3 = pk(vb.z, vb.w), pB4 = pk(vb.w, vbR);

                u64 n001 = mul2(Wp[0][1][0], p00), n023 = mul2(Wp[0][1][3], p02);
                u64 n101 = mul2(Wp[1][0][0], p00), n123 = mul2(Wp[1][0][3], p02);
                fma2(n001, Wp[0][1][1], p01); fma2(n023, Wp[0][1][4], p03);
                fma2(n101, Wp[1][0][1], p01); fma2(n123, Wp[1][0][4], p03);
                fma2(n001, Wp[0][1][2], p02); fma2(n023, Wp[0][1][5], p04);
                fma2(n101, Wp[1][0][2], p02); fma2(n123, Wp[1][0][5], p04);

                fma2(n001, Wp[0][2][0], p10); fma2(n023, Wp[0][2][3], p12);
                fma2(n101, Wp[1][1][0], p10); fma2(n123, Wp[1][1][3], p12);
                fma2(n001, Wp[0][2][1], p11); fma2(n023, Wp[0][2][4], p13);
                fma2(n101, Wp[1][1][1], p11); fma2(n123, Wp[1][1][4], p13);
                fma2(n001, Wp[0][2][2], p12); fma2(n023, Wp[0][2][5], p14);
                fma2(n101, Wp[1][1][2], p12); fma2(n123, Wp[1][1][5], p14);

                fma2(n001, Wp[0][0][0], pA0); fma2(n023, Wp[0][0][3], pA2);
                fma2(n101, Wp[1][2][0], pB0); fma2(n123, Wp[1][2][3], pB2);
                fma2(n001, Wp[0][0][1], pA1); fma2(n023, Wp[0][0][4], pA3);
                fma2(n101, Wp[1][2][1], pB1); fma2(n123, Wp[1][2][4], pB3);
                fma2(n001, Wp[0][0][2], pA2); fma2(n023, Wp[0][0][5], pA4);
                fma2(n101, Wp[1][2][2], pB2); fma2(n123, Wp[1][2][5], pB4);

                upk(n001, y0.x, y0.y); upk(n023, y0.z, y0.w);
                upk(n101, y1.x, y1.y); upk(n123, y1.z, y1.w);

                if (s < STEPS - 1) {
                    const int nb = cb ^ 1;
                    *(float4*)&buf[nb][g2][col0]     = y0;
                    *(float4*)&buf[nb][g2 + 1][col0] = y1;
                }
            }
            if (s < STEPS - 1) __syncthreads();
        }

        // ---- output: ONLY warps 4..15 (region rows 8..31 = the 24 tile rows)
        if (warp >= 4 && warp < 16) {
            const int orow = t0 + g2 - 8;
            if (orow < H) {
                float* ob = out + (size_t)img * IMG + orow * W + col0;
                *(float4*)ob       = y0;
                *(float4*)(ob + W) = y1;
            }
        }
        t = tn;
        // Cross-tile safety: next prologue writes buf[0] only; the last
        // meaningful buf[0] reads were step 6, fenced by the step-6 barrier.
        // Staging reuse fenced by mbar + post-prologue barrier. tkt slot is
        // rewritten only after the barrier at which all warps read it.
    }
}

extern "C" void kernel_launch(void* const* d_in, const int* in_sizes, int n_in,
                              void* d_out, int out_size)
{
    const float* x   = (const float*)d_in[0];
    const float* wgt = (const float*)d_in[1];
    float* out       = (float*)d_out;

    int sms = 152;
    cudaDeviceGetAttribute(&sms, cudaDevAttrMultiProcessorCount, 0);
    if (sms < 1) sms = 152;
    if (sms > NT) sms = NT;

    cudaFuncSetAttribute(diffusion_persist_kernel,
                         cudaFuncAttributeMaxDynamicSharedMemorySize, SMEM_TOTAL);
    reset_ticket_kernel<<<1, 1>>>();
    diffusion_persist_kernel<<<sms, THREADS, SMEM_TOTAL>>>(x, wgt, out);
}

// round 17
// speedup vs baseline: 1.3028x; 1.3028x over previous
#include <cuda_runtime.h>

// x:      (4, 64, 128, 128) fp32  -> 256 independent 128x128 images
// weight: (4, 576, 128, 128) fp32 -> 9 taps per channel, tap k strided by H*W
// steps = 8
//
// TH=20 tall-tile variant of the R14 champion (55.4us), reg-feasible:
//  - 18 warps (576 thr, reg cap 112 vs ~118 natural: small squeeze, unlike
//    R16's fatal 96-vs-120), V=2, region 36 rows + 2 guard rows
//  - FULL R14 mechanism: TMA staging for weights AND x (10 issuers,
//    mbar count 10), guard rows, hoisted own-row operands, clamped scalar
//    LDS laterals, mul2 chain starts
//  - shrinking-band elision: warp g computes step s iff s < min(2g+1,35-2g)
//    (28 warp-steps per SMSP - perfectly balanced)
//  - NT = 256*7 = 1792 (-12.5% prologues/convoys vs TH=16)
//  - output: warps 4..13 (region rows 8..27), orow<H clamp for last tile

#define H      128
#define W      128
#define IMG    (H * W)
#define STEPS  8
#define TH     20
#define TPI    7            // ceil(128/20); last tile covers 8 rows
#define NT     (256 * TPI)  // 1792
#define RROWS  36
#define SROWS  38           // +2 guard rows
#define THREADS 576

#define OFF_MBAR 0
#define OFF_BUF  1024
#define OFF_WS   (OFF_BUF + 2 * SROWS * W * 4)   // 1024 + 38912  = 39936
#define OFF_XS   (OFF_WS + 9 * RROWS * W * 4)    // + 165888      = 205824
#define SMEM_TOTAL (OFF_XS + RROWS * W * 4)      // + 18432       = 224256

typedef unsigned long long u64;
typedef unsigned int u32;

__device__ __forceinline__ u32 s2u(const void* p) {
    u32 a;
    asm("{ .reg .u64 t; cvta.to.shared.u64 t, %1; cvt.u32.u64 %0, t; }"
        : "=r"(a) : "l"(p));
    return a;
}
__device__ __forceinline__ u64 pk(float lo, float hi) {
    u64 r; asm("mov.b64 %0, {%1,%2};" : "=l"(r) : "f"(lo), "f"(hi)); return r;
}
__device__ __forceinline__ void upk(u64 v, float& lo, float& hi) {
    asm("mov.b64 {%0,%1}, %2;" : "=f"(lo), "=f"(hi) : "l"(v));
}
__device__ __forceinline__ void fma2(u64& d, u64 a, u64 b) {
    asm("fma.rn.f32x2 %0, %1, %2, %0;" : "+l"(d) : "l"(a), "l"(b));
}
__device__ __forceinline__ u64 mul2(u64 a, u64 b) {
    u64 d; asm("mul.rn.f32x2 %0, %1, %2;" : "=l"(d) : "l"(a), "l"(b)); return d;
}
__device__ __forceinline__ float shup(float v) { return __shfl_up_sync(0xffffffffu, v, 1); }
__device__ __forceinline__ float shdn(float v) { return __shfl_down_sync(0xffffffffu, v, 1); }

__device__ __forceinline__ void mbar_wait(u32 mbar, u32 parity) {
    asm volatile(
        "{\n\t.reg .pred P;\n\t"
        "W_%=:\n\t"
        "mbarrier.try_wait.parity.shared::cta.b64 P, [%0], %1, 0x989680;\n\t"
        "@P bra.uni D_%=;\n\t"
        "bra.uni W_%=;\n\t"
        "D_%=:\n\t}"
        :: "r"(mbar), "r"(parity) : "memory");
}
__device__ __forceinline__ void bulk_g2s(u32 dst, const void* src, u32 bytes, u32 mbar) {
    asm volatile(
        "cp.async.bulk.shared::cluster.global.mbarrier::complete_tx::bytes "
        "[%0], [%1], %2, [%3];"
        :: "r"(dst), "l"(src), "r"(bytes), "r"(mbar) : "memory");
}

// Distributed prefetch: issuer k (0..8 = weight tap k, 9 = x); mbar count 10.
__device__ __forceinline__ void issue_prefetch_k(int t, int k,
                                                 const float* x, const float* wgt,
                                                 u32 ws, u32 xs, u32 mbar) {
    const int img = t / TPI;
    const int t0  = (t % TPI) * TH;
    const int rlo = (t0 - 8 < 0) ? 0 : (t0 - 8);
    const int rhi = (t0 + 28 > H) ? H : (t0 + 28);
    const int nrows = rhi - rlo;
    const int droff = rlo - (t0 - 8);
    const u32 bytes = (u32)nrows * (W * 4);
    asm volatile("mbarrier.arrive.expect_tx.shared.b64 _, [%0], %1;"
                 :: "r"(mbar), "r"(bytes) : "memory");
    if (k < 9) {
        const float* src = wgt + ((size_t)(img * 9 + k) << 14) + rlo * W;
        bulk_g2s(ws + (u32)(k * RROWS + droff) * (W * 4), src, bytes, mbar);
    } else {
        bulk_g2s(xs + (u32)droff * (W * 4), x + ((size_t)img << 14) + rlo * W, bytes, mbar);
    }
}

__global__ __launch_bounds__(THREADS, 1)
void diffusion_persist_kernel(const float* __restrict__ x,
                              const float* __restrict__ wgt,
                              float* __restrict__ out)
{
    extern __shared__ char smem[];
    float (*buf)[SROWS][W] = (float (*)[SROWS][W])(smem + OFF_BUF);
    const float* wsp = (const float*)(smem + OFF_WS);
    const float* xsp = (const float*)(smem + OFF_XS);
    const u32 mbar = s2u(smem + OFF_MBAR);
    const u32 ws_a = s2u(smem + OFF_WS);
    const u32 xs_a = s2u(smem + OFF_XS);

    const int tid  = threadIdx.x;
    const int lane = tid & 31;
    const int warp = tid >> 5;          // 0..17; owns region rows 2g, 2g+1
    const int col0 = lane << 2;
    const int g2   = warp * 2;
    // Clamped lateral columns: the clamped lanes' values hit zeroed weights.
    const int colL = (lane == 0)  ? col0     : col0 - 1;
    const int colR = (lane == 31) ? col0 + 3 : col0 + 4;
    const bool issuer = (lane == 0 && warp < 10);
    // shrinking-band bound: compute step s iff s < nmax
    const int nmax = (g2 + 1 < 35 - g2) ? (g2 + 1) : (35 - g2);

    // one-time init: guard rows (buf rows 0 and 37 -> zero forever), mbar
    if (tid < 128) {
        int b = tid >> 6, r = (tid >> 5) & 1;
        *(float4*)&buf[b][r ? (SROWS - 1) : 0][(tid & 31) << 2] =
            make_float4(0.f, 0.f, 0.f, 0.f);
    }
    if (tid == 0) {
        asm volatile("mbarrier.init.shared.b64 [%0], 10;" :: "r"(mbar) : "memory");
    }
    __syncthreads();

    int t = blockIdx.x;
    const int stride = gridDim.x;
    if (issuer && t < NT) issue_prefetch_k(t, warp, x, wgt, ws_a, xs_a, mbar);
    u32 ph = 0;

    for (; t < NT; t += stride) {
        mbar_wait(mbar, ph); ph ^= 1u;

        const int img = t / TPI;
        const int t0  = (t % TPI) * TH;

        // ---- tile prologue: weights staging -> normalized packed registers
        u64 Wp[2][3][6];
        float4 y0, y1;
#pragma unroll
        for (int ro = 0; ro < 2; ro++) {
            const int rr   = g2 + ro;
            const int grow = t0 - 8 + rr;
            const bool rv  = ((unsigned)grow < (unsigned)H);
            float aa[9][4];
            if (rv) {
                float s0 = 0.f, s1 = 0.f, s2 = 0.f, s3 = 0.f;
#pragma unroll
                for (int k = 0; k < 9; k++) {
                    float4 tv = *(const float4*)&wsp[(k * RROWS + rr) * W + col0];
                    aa[k][0] = fabsf(tv.x); aa[k][1] = fabsf(tv.y);
                    aa[k][2] = fabsf(tv.z); aa[k][3] = fabsf(tv.w);
                    s0 += aa[k][0]; s1 += aa[k][1]; s2 += aa[k][2]; s3 += aa[k][3];
                }
                const float i0 = __fdividef(1.f, s0), i1 = __fdividef(1.f, s1);
                const float i2 = __fdividef(1.f, s2), i3 = __fdividef(1.f, s3);
#pragma unroll
                for (int k = 0; k < 9; k++) {
                    aa[k][0] *= i0; aa[k][1] *= i1; aa[k][2] *= i2; aa[k][3] *= i3;
                }
                if (lane == 0)  { aa[0][0] = 0.f; aa[3][0] = 0.f; aa[6][0] = 0.f; }
                if (lane == 31) { aa[2][3] = 0.f; aa[5][3] = 0.f; aa[8][3] = 0.f; }
            } else {
#pragma unroll
                for (int k = 0; k < 9; k++) {
                    aa[k][0] = 0.f; aa[k][1] = 0.f; aa[k][2] = 0.f; aa[k][3] = 0.f;
                }
            }
#pragma unroll
            for (int ki = 0; ki < 3; ki++) {
                Wp[ro][ki][0] = pk(aa[ki * 3 + 0][0], aa[ki * 3 + 0][1]);
                Wp[ro][ki][1] = pk(aa[ki * 3 + 1][0], aa[ki * 3 + 1][1]);
                Wp[ro][ki][2] = pk(aa[ki * 3 + 2][0], aa[ki * 3 + 2][1]);
                Wp[ro][ki][3] = pk(aa[ki * 3 + 0][2], aa[ki * 3 + 0][3]);
                Wp[ro][ki][4] = pk(aa[ki * 3 + 1][2], aa[ki * 3 + 1][3]);
                Wp[ro][ki][5] = pk(aa[ki * 3 + 2][2], aa[ki * 3 + 2][3]);
            }
            float4 xv = make_float4(0.f, 0.f, 0.f, 0.f);
            if (rv) xv = *(const float4*)&xsp[rr * W + col0];
            if (ro == 0) y0 = xv; else y1 = xv;
            *(float4*)&buf[0][rr + 1][col0] = xv;
        }

        // hoisted own-row operands for step 0 (register-only; pre-barrier)
        u64 p00, p01, p02, p03, p04, p10, p11, p12, p13, p14;
        {
            const float xl0 = shup(y0.w), xr0 = shdn(y0.x);
            const float xl1 = shup(y1.w), xr1 = shdn(y1.x);
            p00 = pk(xl0, y0.x); p01 = pk(y0.x, y0.y); p02 = pk(y0.y, y0.z);
            p03 = pk(y0.z, y0.w); p04 = pk(y0.w, xr0);
            p10 = pk(xl1, y1.x); p11 = pk(y1.x, y1.y); p12 = pk(y1.y, y1.z);
            p13 = pk(y1.z, y1.w); p14 = pk(y1.w, xr1);
        }
        __syncthreads();   // staging consumed + buf[0] published

        // prefetch next tile (distributed; overlaps the 8-step loop)
        if (issuer && t + stride < NT)
            issue_prefetch_k(t + stride, warp, x, wgt, ws_a, xs_a, mbar);

        // ---- 8 fused steps with shrinking-band elision (R14 body)
#pragma unroll
        for (int s = 0; s < STEPS; s++) {
            if (s < nmax) {
                const int cb = s & 1;
                const float* rowA = &buf[cb][g2][0];      // region row 2g-1
                const float* rowB = &buf[cb][g2 + 3][0];  // region row 2g+2
                float4 va = *(const float4*)&rowA[col0];
                const float vaL = rowA[colL], vaR = rowA[colR];
                float4 vb = *(const float4*)&rowB[col0];
                const float vbL = rowB[colL], vbR = rowB[colR];

                const u64 pA0 = pk(vaL, va.x), pA1 = pk(va.x, va.y), pA2 = pk(va.y, va.z);
                const u64 pA3 = pk(va.z, va.w), pA4 = pk(va.w, vaR);
                const u64 pB0 = pk(vbL, vb.x), pB1 = pk(vb.x, vb.y), pB2 = pk(vb.y, vb.z);
                const u64 pB3 = pk(vb.z, vb.w), pB4 = pk(vb.w, vbR);

                u64 n001 = mul2(Wp[0][1][0], p00), n023 = mul2(Wp[0][1][3], p02);
                u64 n101 = mul2(Wp[1][0][0], p00), n123 = mul2(Wp[1][0][3], p02);
                fma2(n001, Wp[0][1][1], p01); fma2(n023, Wp[0][1][4], p03);
                fma2(n101, Wp[1][0][1], p01); fma2(n123, Wp[1][0][4], p03);
                fma2(n001, Wp[0][1][2], p02); fma2(n023, Wp[0][1][5], p04);
                fma2(n101, Wp[1][0][2], p02); fma2(n123, Wp[1][0][5], p04);

                fma2(n001, Wp[0][2][0], p10); fma2(n023, Wp[0][2][3], p12);
                fma2(n101, Wp[1][1][0], p10); fma2(n123, Wp[1][1][3], p12);
                fma2(n001, Wp[0][2][1], p11); fma2(n023, Wp[0][2][4], p13);
                fma2(n101, Wp[1][1][1], p11); fma2(n123, Wp[1][1][4], p13);
                fma2(n001, Wp[0][2][2], p12); fma2(n023, Wp[0][2][5], p14);
                fma2(n101, Wp[1][1][2], p12); fma2(n123, Wp[1][1][5], p14);

                fma2(n001, Wp[0][0][0], pA0); fma2(n023, Wp[0][0][3], pA2);
                fma2(n101, Wp[1][2][0], pB0); fma2(n123, Wp[1][2][3], pB2);
                fma2(n001, Wp[0][0][1], pA1); fma2(n023, Wp[0][0][4], pA3);
                fma2(n101, Wp[1][2][1], pB1); fma2(n123, Wp[1][2][4], pB3);
                fma2(n001, Wp[0][0][2], pA2); fma2(n023, Wp[0][0][5], pA4);
                fma2(n101, Wp[1][2][2], pB2); fma2(n123, Wp[1][2][5], pB4);

                upk(n001, y0.x, y0.y); upk(n023, y0.z, y0.w);
                upk(n101, y1.x, y1.y); upk(n123, y1.z, y1.w);

                if (s < STEPS - 1) {
                    // hoist next step's own-row operands BEFORE the barrier
                    const float xl0 = shup(y0.w), xr0 = shdn(y0.x);
                    const float xl1 = shup(y1.w), xr1 = shdn(y1.x);
                    p00 = pk(xl0, y0.x); p01 = pk(y0.x, y0.y); p02 = pk(y0.y, y0.z);
                    p03 = pk(y0.z, y0.w); p04 = pk(y0.w, xr0);
                    p10 = pk(xl1, y1.x); p11 = pk(y1.x, y1.y); p12 = pk(y1.y, y1.z);
                    p13 = pk(y1.z, y1.w); p14 = pk(y1.w, xr1);

                    const int nb = cb ^ 1;
                    *(float4*)&buf[nb][g2 + 1][col0] = y0;
                    *(float4*)&buf[nb][g2 + 2][col0] = y1;
                }
            }
            if (s < STEPS - 1) __syncthreads();
        }

        // ---- output: warps 4..13 hold region rows 8..27 = the 20 tile rows
        if ((unsigned)(warp - 4) < 10u) {
            const int orow = t0 + g2 - 8;      // even; orow<H => orow+1<H
            if (orow < H) {
                float* ob = out + (size_t)img * IMG + orow * W + col0;
                *(float4*)ob       = y0;
                *(float4*)(ob + W) = y1;
            }
        }
        // Cross-tile safety (as R14): next prologue writes buf[0] only; the
        // last meaningful buf[0] reads were step 6, fenced by the step-6
        // barrier. Staging reuse fenced by mbar + post-prologue barrier.
    }
}

extern "C" void kernel_launch(void* const* d_in, const int* in_sizes, int n_in,
                              void* d_out, int out_size)
{
    const float* x   = (const float*)d_in[0];
    const float* wgt = (const float*)d_in[1];
    float* out       = (float*)d_out;

    int sms = 152;
    cudaDeviceGetAttribute(&sms, cudaDevAttrMultiProcessorCount, 0);
    if (sms < 1) sms = 152;
    if (sms > NT) sms = NT;

    cudaFuncSetAttribute(diffusion_persist_kernel,
                         cudaFuncAttributeMaxDynamicSharedMemorySize, SMEM_TOTAL);
    diffusion_persist_kernel<<<sms, THREADS, SMEM_TOTAL>>>(x, wgt, out);
}